// round 13
// baseline (speedup 1.0000x reference)
#include <cuda_runtime.h>
#include <cuda_fp16.h>

#define Bn 32
#define Cn 32
#define Gn 4096
#define Nn 16384
#define Hn 64
#define WT_BLOCKS 5
#define SCAT_BLOCKS Bn                       // 32
#define CG_BLOCKS ((Bn * Gn) / 256)          // 512 (16 per batch)
#define MLP_BLOCKS ((Bn * Nn) / 256)         // 2048 (64 per batch)
#define CG_BASE   (WT_BLOCKS + SCAT_BLOCKS)  // 37
#define MLP_BASE  (CG_BASE + CG_BLOCKS)      // 549

typedef unsigned long long u64;

// slot -> cell index (materialized by scatter; replaces searchsorted)
__device__ int g_idx[Bn * Nn];
// per-cell layer-1 pre-activations in fp16, 8 halves per uint4 row
__device__ uint4 g_Ah[(size_t)Bn * 8 * Gn];     // 16 MB
// progress flags (all self-resetting within one launch -> replay-safe)
__device__ int g_flag = 0;                      // weights ready (== WT_BLOCKS)
__device__ int g_cg_entered = 0;                // cg blocks past compute
__device__ int g_done[Bn];                      // scatter(1) + cg(16) per batch
__device__ int g_mlp_entered[Bn];               // mlp blocks past compute

// ---- packed f32x2 helpers --------------------------------------------------
static __device__ __forceinline__ u64 pk(float lo, float hi) {
    u64 r; asm("mov.b64 %0, {%1, %2};" : "=l"(r) : "f"(lo), "f"(hi)); return r;
}
static __device__ __forceinline__ void upk(float& lo, float& hi, u64 v) {
    asm("mov.b64 {%0, %1}, %2;" : "=f"(lo), "=f"(hi) : "l"(v));
}
static __device__ __forceinline__ u64 fma2(u64 a, u64 b, u64 c) {
    u64 d; asm("fma.rn.f32x2 %0, %1, %2, %3;" : "=l"(d) : "l"(a), "l"(b), "l"(c));
    return d;
}
static __device__ __forceinline__ unsigned cvt_h2(u64 v) {
    float lo, hi; upk(lo, hi, v);
    unsigned r;
    asm("cvt.rn.f16x2.f32 %0, %1, %2;" : "=r"(r) : "f"(hi), "f"(lo));
    return r;
}
static __device__ __forceinline__ u64 h2pk(unsigned h) {
    __half2 hv = *reinterpret_cast<__half2*>(&h);
    float2 f = __half22float2(hv);
    return pk(f.x, f.y);
}

// ---- weight blob: lives in constant space, written in-place ----------------
struct __align__(16) WBlob {
    u64 w1T[Cn][32];     // [c][hp] = pk(W1[2hp][c], W1[2hp+1][c])
    u64 b1p[32];
    u64 w32p[32];
    u64 w33p[32];
    u64 w2xp[32];
    u64 w2yp[32];
    u64 w2zp[32];
    float b2v[4];
};
__constant__ WBlob c_blob;

// ---------------------------------------------------------------------------
// ONE kernel, four roles by block range (producers always at lower bids):
//   [0,5): weight transform -> flag   [5,37): scatter -> g_done[b] += 1
//   [37,549): cellgemm (waits flag) -> g_done[b] += 1 each (16/batch)
//   [549,2597): mlp (waits g_done[b]==17)
// ---------------------------------------------------------------------------
__global__ __launch_bounds__(256) void mega_kernel(WBlob* __restrict__ blob,
                                                   const float* __restrict__ x,
                                                   const int* __restrict__ counts,
                                                   const float* __restrict__ W1,
                                                   const float* __restrict__ b1,
                                                   const float* __restrict__ W2,
                                                   const float* __restrict__ b2,
                                                   const float* __restrict__ b_rnd,
                                                   const float* __restrict__ grid_o,
                                                   float* __restrict__ out,
                                                   float* __restrict__ reg_out)
{
    const int t = threadIdx.x;

    if (blockIdx.x < WT_BLOCKS) {
        // ---- weight transform ----
        if (blockIdx.x < 4) {
            const int i = blockIdx.x * 256 + t;
            const int c = i >> 5, hp = i & 31;
            blob->w1T[c][hp] = pk(W1[(2 * hp) * 34 + c], W1[(2 * hp + 1) * 34 + c]);
        } else {
            if (t < 32) {
                blob->b1p[t]  = pk(b1[2 * t], b1[2 * t + 1]);
                blob->w32p[t] = pk(W1[(2 * t) * 34 + 32], W1[(2 * t + 1) * 34 + 32]);
                blob->w33p[t] = pk(W1[(2 * t) * 34 + 33], W1[(2 * t + 1) * 34 + 33]);
                blob->w2xp[t] = pk(W2[2 * t],            W2[2 * t + 1]);
                blob->w2yp[t] = pk(W2[Hn + 2 * t],       W2[Hn + 2 * t + 1]);
                blob->w2zp[t] = pk(W2[2 * Hn + 2 * t],   W2[2 * Hn + 2 * t + 1]);
            }
            if (t < 3) blob->b2v[t] = b2[t];
            if (t == 3) blob->b2v[3] = 0.f;
        }
        __syncthreads();
        __threadfence();
        if (t == 0) atomicAdd(&g_flag, 1);
        return;
    }

    if (blockIdx.x < CG_BASE) {
        // ---- cumsum + scatter for one batch ----
        const int b = blockIdx.x - WT_BLOCKS;
        __shared__ int wsum[8];
        const int lane = t & 31;
        const int w    = t >> 5;
        const int base = t * 16;

        int local[16];
        int s = 0;
#pragma unroll
        for (int i = 0; i < 16; i++) {
            s += counts[b * Gn + base + i];
            local[i] = s;
        }
        int v = s;
#pragma unroll
        for (int d = 1; d < 32; d <<= 1) {
            int u = __shfl_up_sync(0xffffffff, v, d);
            if (lane >= d) v += u;
        }
        if (lane == 31) wsum[w] = v;
        __syncthreads();
        int woff = 0;
        for (int i = 0; i < w; i++) woff += wsum[i];
        const int excl = woff + v - s;

        int* gi = g_idx + b * Nn;
        int start = excl;
#pragma unroll
        for (int i = 0; i < 16; i++) {
            const int end = excl + local[i];
            const int cell = base + i;
            for (int j = start; j < end; j++) gi[j] = cell;
            start = end;
        }
        __syncthreads();
        __threadfence();
        if (t == 0) atomicAdd(&g_done[b], 1);
        return;
    }

    if (blockIdx.x < MLP_BASE) {
        // ---- cellgemm: wait for weights, compute, publish ----
        if (t == 0) {
            while (atomicAdd(&g_flag, 0) < WT_BLOCKS) __nanosleep(64);
        }
        __syncthreads();

        const int gid  = (blockIdx.x - CG_BASE) * 256 + t;   // covers Bn*Gn
        const int b    = gid >> 12;
        const int cell = gid & (Gn - 1);

        u64 acc[32];
#pragma unroll
        for (int hp = 0; hp < 32; hp++) acc[hp] = c_blob.b1p[hp];

        const float* xb = x + (size_t)b * Cn * Gn + cell;
#pragma unroll 4
        for (int c = 0; c < Cn; c++) {
            float xv = __ldg(xb + c * Gn);
            u64 xp = pk(xv, xv);
#pragma unroll
            for (int hp = 0; hp < 32; hp++)
                acc[hp] = fma2(c_blob.w1T[c][hp], xp, acc[hp]);
        }

        const int cnt = __ldg(counts + b * Gn + cell);
        if (cnt != 0) {
            uint4* Ah = g_Ah + (size_t)b * 8 * Gn + cell;
#pragma unroll
            for (int q = 0; q < 8; q++)
                Ah[q * Gn] = make_uint4(cvt_h2(acc[4 * q]),     cvt_h2(acc[4 * q + 1]),
                                        cvt_h2(acc[4 * q + 2]), cvt_h2(acc[4 * q + 3]));
        }
        __syncthreads();
        __threadfence();
        if (t == 0) {
            atomicAdd(&g_done[b], 1);
            // 512th cg block past the flag-wait resets the weight flag
            int e = atomicAdd(&g_cg_entered, 1);
            if (e == CG_BLOCKS - 1) { g_cg_entered = 0; g_flag = 0; }
        }
        return;
    }

    // ---- mlp: wait for this batch's scatter + 16 cellgemm blocks ----
    const int m = blockIdx.x - MLP_BASE;         // 0..2047
    const int b = m >> 6;                        // batch (64 blocks each)
    if (t == 0) {
        while (atomicAdd(&g_done[b], 0) < 17) __nanosleep(128);
    }
    __syncthreads();
    __threadfence();

    const int j = (m & 63) * 256 + t;

    const int idx = __ldg(g_idx + b * Nn + j);

    u64 a2[32];
    const uint4* Ah = g_Ah + (size_t)b * 8 * Gn + idx;
#pragma unroll
    for (int q = 0; q < 8; q++) {
        uint4 v = __ldg(Ah + q * Gn);
        a2[4 * q]     = h2pk(v.x);
        a2[4 * q + 1] = h2pk(v.y);
        a2[4 * q + 2] = h2pk(v.z);
        a2[4 * q + 3] = h2pk(v.w);
    }

    const float* br = b_rnd + (size_t)b * 2 * Nn;
    const float r0 = br[j], r1 = br[Nn + j];
    const u64 rp0 = pk(r0, r0), rp1 = pk(r1, r1);

    u64 oX2 = 0ull, oY2 = 0ull, oZ2 = 0ull;
#pragma unroll
    for (int hp = 0; hp < 32; hp++) {
        u64 pre = fma2(c_blob.w32p[hp], rp0, a2[hp]);
        pre     = fma2(c_blob.w33p[hp], rp1, pre);
        float plo, phi;
        upk(plo, phi, pre);
        plo = fmaxf(plo, 0.f);
        phi = fmaxf(phi, 0.f);
        u64 act = pk(plo, phi);
        oX2 = fma2(c_blob.w2xp[hp], act, oX2);
        oY2 = fma2(c_blob.w2yp[hp], act, oY2);
        oZ2 = fma2(c_blob.w2zp[hp], act, oZ2);
    }

    float xl, xh, yl, yh, zl, zh;
    upk(xl, xh, oX2); upk(yl, yh, oY2); upk(zl, zh, oZ2);
    const float o0 = c_blob.b2v[0] + xl + xh;
    const float o1 = c_blob.b2v[1] + yl + yh;
    const float o2 = c_blob.b2v[2] + zl + zh;

    const float thr = 0.10825317547305482f;  // sqrt(3)/16
    const float nrm = sqrtf(o0 * o0 + o1 * o1 + o2 * o2);

    float* outb = out + (size_t)b * 3 * Nn;
    __stcs(outb + j,          o0 + __ldg(grid_o + idx));
    __stcs(outb + Nn + j,     o1 + __ldg(grid_o + Gn + idx));
    __stcs(outb + 2 * Nn + j, o2 + __ldg(grid_o + 2 * Gn + idx));
    __stcs(reg_out + b * Nn + j, fmaxf(nrm - thr, 0.f));

    // 64th mlp block of this batch (all past the wait) resets batch counters
    if (t == 0) {
        int e = atomicAdd(&g_mlp_entered[b], 1);
        if (e == 63) { g_mlp_entered[b] = 0; g_done[b] = 0; }
    }
}

extern "C" void kernel_launch(void* const* d_in, const int* in_sizes, int n_in,
                              void* d_out, int out_size)
{
    const float* x      = (const float*)d_in[0];
    const int*   counts = (const int*)  d_in[1];
    const float* b_rnd  = (const float*)d_in[2];
    const float* grid_o = (const float*)d_in[3];
    const float* W1     = (const float*)d_in[4];
    const float* b1     = (const float*)d_in[5];
    const float* W2     = (const float*)d_in[6];
    const float* b2     = (const float*)d_in[7];

    float* out     = (float*)d_out;              // (B, 3, N)
    float* reg_out = out + (size_t)Bn * 3 * Nn;  // (B, N)

    void* c_addr = nullptr;
    cudaGetSymbolAddress(&c_addr, c_blob);

    mega_kernel<<<MLP_BASE + MLP_BLOCKS, 256>>>(
        (WBlob*)c_addr, x, counts, W1, b1, W2, b2, b_rnd, grid_o, out, reg_out);
}

// round 14
// speedup vs baseline: 1.0788x; 1.0788x over previous
#include <cuda_runtime.h>
#include <cuda_fp16.h>

#define Bn 32
#define Cn 32
#define Gn 4096
#define Nn 16384
#define Hn 64
#define WT_BLOCKS 5
#define SCAT_BLOCKS Bn
#define CG_BLOCKS ((Bn * Gn * 2) / 256)   // 1024: (cell, hf) units
#define CG_BASE (WT_BLOCKS + SCAT_BLOCKS)

typedef unsigned long long u64;

// slot -> cell index (materialized by scatter; replaces searchsorted)
__device__ int g_idx[Bn * Nn];
// per-cell layer-1 pre-activations in fp16, 8 halves per uint4 row
__device__ uint4 g_Ah[(size_t)Bn * 8 * Gn];     // 16 MB
// weights-ready flag: set to WT_BLOCKS by weight blocks, reset by mlp_kernel
__device__ int g_flag = 0;

// ---- packed f32x2 helpers --------------------------------------------------
static __device__ __forceinline__ u64 pk(float lo, float hi) {
    u64 r; asm("mov.b64 %0, {%1, %2};" : "=l"(r) : "f"(lo), "f"(hi)); return r;
}
static __device__ __forceinline__ void upk(float& lo, float& hi, u64 v) {
    asm("mov.b64 {%0, %1}, %2;" : "=f"(lo), "=f"(hi) : "l"(v));
}
static __device__ __forceinline__ u64 fma2(u64 a, u64 b, u64 c) {
    u64 d; asm("fma.rn.f32x2 %0, %1, %2, %3;" : "=l"(d) : "l"(a), "l"(b), "l"(c));
    return d;
}
static __device__ __forceinline__ unsigned cvt_h2(u64 v) {
    float lo, hi; upk(lo, hi, v);
    unsigned r;
    asm("cvt.rn.f16x2.f32 %0, %1, %2;" : "=r"(r) : "f"(hi), "f"(lo));
    return r;
}
static __device__ __forceinline__ u64 h2pk(unsigned h) {
    __half2 hv = *reinterpret_cast<__half2*>(&h);
    float2 f = __half22float2(hv);
    return pk(f.x, f.y);
}

// ---- weight blob: lives in constant space, written in-place by fused -------
struct __align__(16) WBlob {
    u64 w1T[Cn][32];     // [c][hp] = pk(W1[2hp][c], W1[2hp+1][c])
    u64 b1p[32];
    u64 w32p[32];
    u64 w33p[32];
    u64 w2xp[32];
    u64 w2yp[32];
    u64 w2zp[32];
    float b2v[4];
};
__constant__ WBlob c_blob;

// ---------------------------------------------------------------------------
// Kernel 1 (fused): [0,5) weight transform; [5,37) scatter;
//   [37,1061) cellgemm with h split by BLOCK: each thread = 1 cell x 16 hp
//   (32 acc regs -> ~5 CTAs/SM). hf interleaved fastest for L2 x-reuse.
// ---------------------------------------------------------------------------
__global__ __launch_bounds__(256) void fused_kernel(WBlob* __restrict__ blob,
                                                    const float* __restrict__ x,
                                                    const int* __restrict__ counts,
                                                    const float* __restrict__ W1,
                                                    const float* __restrict__ b1,
                                                    const float* __restrict__ W2,
                                                    const float* __restrict__ b2)
{
    const int t = threadIdx.x;

    if (blockIdx.x < WT_BLOCKS) {
        // ---- weight transform ----
        if (blockIdx.x < 4) {
            const int i = blockIdx.x * 256 + t;
            const int c = i >> 5, hp = i & 31;
            blob->w1T[c][hp] = pk(W1[(2 * hp) * 34 + c], W1[(2 * hp + 1) * 34 + c]);
        } else {
            if (t < 32) {
                blob->b1p[t]  = pk(b1[2 * t], b1[2 * t + 1]);
                blob->w32p[t] = pk(W1[(2 * t) * 34 + 32], W1[(2 * t + 1) * 34 + 32]);
                blob->w33p[t] = pk(W1[(2 * t) * 34 + 33], W1[(2 * t + 1) * 34 + 33]);
                blob->w2xp[t] = pk(W2[2 * t],            W2[2 * t + 1]);
                blob->w2yp[t] = pk(W2[Hn + 2 * t],       W2[Hn + 2 * t + 1]);
                blob->w2zp[t] = pk(W2[2 * Hn + 2 * t],   W2[2 * Hn + 2 * t + 1]);
            }
            if (t < 3) blob->b2v[t] = b2[t];
            if (t == 3) blob->b2v[3] = 0.f;
        }
        __syncthreads();
        __threadfence();
        if (t == 0) atomicAdd(&g_flag, 1);
        return;
    }

    if (blockIdx.x < CG_BASE) {
        // ---- cumsum + scatter for one batch ----
        const int b = blockIdx.x - WT_BLOCKS;
        __shared__ int wsum[8];
        const int lane = t & 31;
        const int w    = t >> 5;
        const int base = t * 16;

        int local[16];
        int s = 0;
#pragma unroll
        for (int i = 0; i < 16; i++) {
            s += counts[b * Gn + base + i];
            local[i] = s;
        }
        int v = s;
#pragma unroll
        for (int d = 1; d < 32; d <<= 1) {
            int u = __shfl_up_sync(0xffffffff, v, d);
            if (lane >= d) v += u;
        }
        if (lane == 31) wsum[w] = v;
        __syncthreads();
        int woff = 0;
        for (int i = 0; i < w; i++) woff += wsum[i];
        const int excl = woff + v - s;

        int* gi = g_idx + b * Nn;
        int start = excl;
#pragma unroll
        for (int i = 0; i < 16; i++) {
            const int end = excl + local[i];
            const int cell = base + i;
            for (int j = start; j < end; j++) gi[j] = cell;
            start = end;
        }
        return;
    }

    // ---- cellgemm: wait for weights, then 1 cell x 16 hp per thread ----
    if (t == 0) {
        while (atomicAdd(&g_flag, 0) < WT_BLOCKS) __nanosleep(64);
    }
    __syncthreads();

    const int cgid = blockIdx.x - CG_BASE;            // 0..1023
    const int hf   = cgid & 1;                        // block-uniform h half
    const int hp0  = hf * 16;                         // uniform -> LDCU path
    const int gid  = (cgid >> 1) * 256 + t;           // covers Bn*Gn
    const int b    = gid >> 12;
    const int cell = gid & (Gn - 1);

    u64 acc[16];
#pragma unroll
    for (int m = 0; m < 16; m++) acc[m] = c_blob.b1p[hp0 + m];

    const float* xb = x + (size_t)b * Cn * Gn + cell;
#pragma unroll 8
    for (int c = 0; c < Cn; c++) {
        float xv = __ldg(xb + c * Gn);
        u64 xp = pk(xv, xv);
#pragma unroll
        for (int m = 0; m < 16; m++)
            acc[m] = fma2(c_blob.w1T[c][hp0 + m], xp, acc[m]);
    }

    const int cnt = __ldg(counts + b * Gn + cell);
    if (cnt != 0) {
        uint4* Ah = g_Ah + ((size_t)b * 8 + hf * 4) * Gn + cell;
#pragma unroll
        for (int q = 0; q < 4; q++)
            Ah[q * Gn] = make_uint4(cvt_h2(acc[4 * q]),     cvt_h2(acc[4 * q + 1]),
                                    cvt_h2(acc[4 * q + 2]), cvt_h2(acc[4 * q + 3]));
    }
}

// ---------------------------------------------------------------------------
// Kernel 2: per-point tail: idx lookup + 8x LDG.128 fp16 gather + tiny MLP.
// Resets g_flag for the next replay (runs strictly after fused).
// ---------------------------------------------------------------------------
__global__ __launch_bounds__(256) void mlp_kernel(
    const float* __restrict__ b_rnd,   // (B, 2, N)
    const float* __restrict__ grid_o,  // (3, G)
    float* __restrict__ out,           // (B, 3, N)
    float* __restrict__ reg_out)       // (B, N)
{
    const int gid = blockIdx.x * 256 + threadIdx.x;  // covers Bn*Nn
    if (gid == 0) g_flag = 0;                        // reset for next launch
    const int b = gid >> 14;
    const int j = gid & (Nn - 1);

    const int idx = __ldg(g_idx + b * Nn + j);

    u64 a2[32];
    const uint4* Ah = g_Ah + (size_t)b * 8 * Gn + idx;
#pragma unroll
    for (int q = 0; q < 8; q++) {
        uint4 v = __ldg(Ah + q * Gn);
        a2[4 * q]     = h2pk(v.x);
        a2[4 * q + 1] = h2pk(v.y);
        a2[4 * q + 2] = h2pk(v.z);
        a2[4 * q + 3] = h2pk(v.w);
    }

    const float* br = b_rnd + (size_t)b * 2 * Nn;
    const float r0 = br[j], r1 = br[Nn + j];
    const u64 rp0 = pk(r0, r0), rp1 = pk(r1, r1);

    u64 oX2 = 0ull, oY2 = 0ull, oZ2 = 0ull;
#pragma unroll
    for (int hp = 0; hp < 32; hp++) {
        u64 pre = fma2(c_blob.w32p[hp], rp0, a2[hp]);
        pre     = fma2(c_blob.w33p[hp], rp1, pre);
        float plo, phi;
        upk(plo, phi, pre);
        plo = fmaxf(plo, 0.f);
        phi = fmaxf(phi, 0.f);
        u64 act = pk(plo, phi);
        oX2 = fma2(c_blob.w2xp[hp], act, oX2);
        oY2 = fma2(c_blob.w2yp[hp], act, oY2);
        oZ2 = fma2(c_blob.w2zp[hp], act, oZ2);
    }

    float xl, xh, yl, yh, zl, zh;
    upk(xl, xh, oX2); upk(yl, yh, oY2); upk(zl, zh, oZ2);
    const float o0 = c_blob.b2v[0] + xl + xh;
    const float o1 = c_blob.b2v[1] + yl + yh;
    const float o2 = c_blob.b2v[2] + zl + zh;

    const float thr = 0.10825317547305482f;  // sqrt(3)/16
    const float nrm = sqrtf(o0 * o0 + o1 * o1 + o2 * o2);

    float* outb = out + (size_t)b * 3 * Nn;
    __stcs(outb + j,          o0 + __ldg(grid_o + idx));
    __stcs(outb + Nn + j,     o1 + __ldg(grid_o + Gn + idx));
    __stcs(outb + 2 * Nn + j, o2 + __ldg(grid_o + 2 * Gn + idx));
    __stcs(reg_out + b * Nn + j, fmaxf(nrm - thr, 0.f));
}

extern "C" void kernel_launch(void* const* d_in, const int* in_sizes, int n_in,
                              void* d_out, int out_size)
{
    const float* x      = (const float*)d_in[0];
    const int*   counts = (const int*)  d_in[1];
    const float* b_rnd  = (const float*)d_in[2];
    const float* grid_o = (const float*)d_in[3];
    const float* W1     = (const float*)d_in[4];
    const float* b1     = (const float*)d_in[5];
    const float* W2     = (const float*)d_in[6];
    const float* b2     = (const float*)d_in[7];

    float* out     = (float*)d_out;              // (B, 3, N)
    float* reg_out = out + (size_t)Bn * 3 * Nn;  // (B, N)

    void* c_addr = nullptr;
    cudaGetSymbolAddress(&c_addr, c_blob);

    fused_kernel<<<CG_BASE + CG_BLOCKS, 256>>>(
        (WBlob*)c_addr, x, counts, W1, b1, W2, b2);
    mlp_kernel<<<(Bn * Nn) / 256, 256>>>(b_rnd, grid_o, out, reg_out);
}